// round 4
// baseline (speedup 1.0000x reference)
#include <cuda_runtime.h>
#include <cstdint>
#include <cstddef>
#include <math.h>

#define T    60
#define NN   10000
#define EE   160000
#define INC  64
#define HIDC 128
#define CAP  64   // per-node neighbor slot capacity (Poisson(16): P(deg>=64) ~ 1e-18)

// ---------------- scratch (static device globals; no allocation) ----------------
__device__ int      g_deg [T * NN];
__device__ int      g_slot[(size_t)T * NN * CAP];   // 153.6 MB bucketed adjacency
__device__ float    g_p   [(size_t)T * NN * 8];     // layer-2 aggregand (padded to 8)
__device__ float    g_rr  [(size_t)T * NN * 8];     // self term of layer 2
__device__ unsigned g_zenc[T * 8];                  // ordered-encoded max per (t, ch)

// ordered float <-> uint encoding for atomicMax
__device__ __forceinline__ unsigned encf(float f) {
    unsigned u = __float_as_uint(f);
    return (u & 0x80000000u) ? ~u : (u | 0x80000000u);
}
__device__ __forceinline__ float decf(unsigned u) {
    return (u & 0x80000000u) ? __uint_as_float(u & 0x7fffffffu) : __uint_as_float(~u);
}

// ---------------- K0: init ----------------
__global__ void k0_init() {
    int idx = blockIdx.x * blockDim.x + threadIdx.x;
    if (idx < T * NN) g_deg[idx] = 0;
    if (idx < T * 8)  g_zenc[idx] = 0u;
}

// ---------------- K1: single-pass bucketed CSR build (4 edges/thread) ----------------
__global__ void k1_build(const int* __restrict__ ei) {
    int q = blockIdx.x * blockDim.x + threadIdx.x;           // quad index
    if (q >= T * (EE / 4)) return;
    int t = q / (EE / 4);
    int e = (q - t * (EE / 4)) * 4;
    const int* sp = ei + (size_t)t * 2 * EE + e;
    int4 sv = *(const int4*)sp;
    int4 dv = *(const int4*)(sp + EE);
    int tb = t * NN;
    int d0 = tb + dv.x, d1 = tb + dv.y, d2 = tb + dv.z, d3 = tb + dv.w;
    int p0 = atomicAdd(&g_deg[d0], 1);
    int p1 = atomicAdd(&g_deg[d1], 1);
    int p2 = atomicAdd(&g_deg[d2], 1);
    int p3 = atomicAdd(&g_deg[d3], 1);
    if (p0 < CAP) g_slot[(size_t)d0 * CAP + p0] = sv.x;
    if (p1 < CAP) g_slot[(size_t)d1 * CAP + p1] = sv.y;
    if (p2 < CAP) g_slot[(size_t)d2 * CAP + p2] = sv.z;
    if (p3 < CAP) g_slot[(size_t)d3 * CAP + p3] = sv.w;
}

// ---------------- K4: fused mean-aggregate + GEMM1(+relu) + layer-2 projections ----------------
// per warp: 4 nodes. mean computed in registers from x gathers, staged to smem,
// then h = relu([mean|x] @ [W1l|W1r].T + b1); p = h@W2l.T; rr = h@W2r.T
__global__ __launch_bounds__(256, 2) void k4_fused(
    const float* __restrict__ x,
    const float* __restrict__ W1l, const float* __restrict__ W1r,
    const float* __restrict__ b1,
    const float* __restrict__ W2l, const float* __restrict__ W2r)
{
    extern __shared__ float sm[];
    float* sWL = sm;                    // [c=64][o=128]  W1l transposed
    float* sWR = sm + 64 * 128;         // [c][o]         W1r transposed
    float* sB1 = sWR + 64 * 128;        // [128]
    float* sMX = sB1 + 128;             // 8 warps * (4 nodes * 2 * 64)
    int tid = threadIdx.x;
    for (int idx = tid; idx < 64 * 128; idx += 256) {
        int c = idx >> 7, o = idx & 127;
        sWL[idx] = W1l[o * 64 + c];
        sWR[idx] = W1r[o * 64 + c];
    }
    if (tid < 128) sB1[tid] = b1[tid];
    __syncthreads();

    int lane = tid & 31;
    int wid  = tid >> 5;
    float w2l[6][4], w2r[6][4];
#pragma unroll
    for (int j = 0; j < 6; j++)
#pragma unroll
        for (int k = 0; k < 4; k++) {
            w2l[j][k] = W2l[j * 128 + 4 * lane + k];
            w2r[j][k] = W2r[j * 128 + 4 * lane + k];
        }
    float b1r[4];
#pragma unroll
    for (int k = 0; k < 4; k++) b1r[k] = sB1[4 * lane + k];

    float* myMX = sMX + wid * 512;      // [mean: 4*64][x: 4*64]
    const float4* WL4 = (const float4*)sWL;
    const float4* WR4 = (const float4*)sWR;

    int warpGlobal = blockIdx.x * 8 + wid;
    int nWarps = gridDim.x * 8;
    const int nGroups = T * NN / 4;

    for (int g = warpGlobal; g < nGroups; g += nWarps) {
        int n0 = g * 4;
        int t  = n0 / NN;
        const float* xt = x + (size_t)t * NN * INC;
        // gather + mean for 4 nodes, plus self row staging
#pragma unroll
        for (int nn = 0; nn < 4; nn++) {
            int node = n0 + nn;
            int deg = g_deg[node];
            int m = min(deg, CAP);
            const int* elist = g_slot + (size_t)node * CAP;
            float sx = 0.f, sy = 0.f;
            int e = 0;
            for (; e + 4 <= m; e += 4) {
                int s0 = elist[e + 0], s1 = elist[e + 1], s2 = elist[e + 2], s3 = elist[e + 3];
                float2 v0 = ((const float2*)(xt + (size_t)s0 * INC))[lane];
                float2 v1 = ((const float2*)(xt + (size_t)s1 * INC))[lane];
                float2 v2 = ((const float2*)(xt + (size_t)s2 * INC))[lane];
                float2 v3 = ((const float2*)(xt + (size_t)s3 * INC))[lane];
                sx += (v0.x + v1.x) + (v2.x + v3.x);
                sy += (v0.y + v1.y) + (v2.y + v3.y);
            }
            for (; e < m; e++) {
                int s0 = elist[e];
                float2 v0 = ((const float2*)(xt + (size_t)s0 * INC))[lane];
                sx += v0.x; sy += v0.y;
            }
            float inv = 1.0f / (float)max(deg, 1);
            float2 xv = ((const float2*)(x + (size_t)node * INC))[lane];
            ((float2*)(myMX + nn * 64))[lane]       = make_float2(sx * inv, sy * inv);
            ((float2*)(myMX + 256 + nn * 64))[lane] = xv;
        }
        __syncwarp();

        float acc[4][4];
#pragma unroll
        for (int nn = 0; nn < 4; nn++)
#pragma unroll
            for (int k = 0; k < 4; k++) acc[nn][k] = b1r[k];

#pragma unroll 8
        for (int c = 0; c < 64; c++) {
            float4 wl = WL4[c * 32 + lane];
            float4 wr = WR4[c * 32 + lane];
#pragma unroll
            for (int nn = 0; nn < 4; nn++) {
                float m  = myMX[nn * 64 + c];
                float xv = myMX[256 + nn * 64 + c];
                acc[nn][0] += wl.x * m + wr.x * xv;
                acc[nn][1] += wl.y * m + wr.y * xv;
                acc[nn][2] += wl.z * m + wr.z * xv;
                acc[nn][3] += wl.w * m + wr.w * xv;
            }
        }

#pragma unroll
        for (int nn = 0; nn < 4; nn++) {
            float h0 = fmaxf(acc[nn][0], 0.f);
            float h1 = fmaxf(acc[nn][1], 0.f);
            float h2 = fmaxf(acc[nn][2], 0.f);
            float h3 = fmaxf(acc[nn][3], 0.f);
            float pl[6], pr[6];
#pragma unroll
            for (int j = 0; j < 6; j++) {
                pl[j] = h0 * w2l[j][0] + h1 * w2l[j][1] + h2 * w2l[j][2] + h3 * w2l[j][3];
                pr[j] = h0 * w2r[j][0] + h1 * w2r[j][1] + h2 * w2r[j][2] + h3 * w2r[j][3];
            }
#pragma unroll
            for (int o = 16; o > 0; o >>= 1) {
#pragma unroll
                for (int j = 0; j < 6; j++) {
                    pl[j] += __shfl_xor_sync(0xffffffffu, pl[j], o);
                    pr[j] += __shfl_xor_sync(0xffffffffu, pr[j], o);
                }
            }
            if (lane == 0) {
                size_t base = (size_t)(n0 + nn) * 8;
#pragma unroll
                for (int j = 0; j < 6; j++) {
                    g_p[base + j]  = pl[j];
                    g_rr[base + j] = pr[j];
                }
            }
        }
    }
}

// ---------------- K6: layer-2 aggregation (6 ch) + global max pool ----------------
__global__ void k6_layer2(const float* __restrict__ b2) {
    int t = blockIdx.x / 40;
    int chunk = blockIdx.x % 40;
    int i = chunk * 256 + threadIdx.x;
    __shared__ unsigned zmax[6];
    if (threadIdx.x < 6) zmax[threadIdx.x] = 0u;
    __syncthreads();
    if (i < NN) {
        int node = t * NN + i;
        int deg = g_deg[node];
        int m = min(deg, CAP);
        const int* elist = g_slot + (size_t)node * CAP;
        float s0=0,s1=0,s2=0,s3=0,s4=0,s5=0;
        int tb = t * NN;
        int e = 0;
        for (; e + 4 <= m; e += 4) {
            int r0 = elist[e+0], r1 = elist[e+1], r2 = elist[e+2], r3 = elist[e+3];
            const float4* q0 = (const float4*)(g_p + (size_t)(tb + r0) * 8);
            const float4* q1 = (const float4*)(g_p + (size_t)(tb + r1) * 8);
            const float4* q2 = (const float4*)(g_p + (size_t)(tb + r2) * 8);
            const float4* q3 = (const float4*)(g_p + (size_t)(tb + r3) * 8);
            float4 a0 = q0[0], b0 = q0[1];
            float4 a1 = q1[0], b1 = q1[1];
            float4 a2 = q2[0], b2v = q2[1];
            float4 a3 = q3[0], b3 = q3[1];
            s0 += (a0.x + a1.x) + (a2.x + a3.x);
            s1 += (a0.y + a1.y) + (a2.y + a3.y);
            s2 += (a0.z + a1.z) + (a2.z + a3.z);
            s3 += (a0.w + a1.w) + (a2.w + a3.w);
            s4 += (b0.x + b1.x) + (b2v.x + b3.x);
            s5 += (b0.y + b1.y) + (b2v.y + b3.y);
        }
        for (; e < m; e++) {
            const float4* q = (const float4*)(g_p + (size_t)(tb + elist[e]) * 8);
            float4 a = q[0], b = q[1];
            s0 += a.x; s1 += a.y; s2 += a.z; s3 += a.w; s4 += b.x; s5 += b.y;
        }
        float inv = 1.0f / (float)max(deg, 1);
        size_t base = (size_t)node * 8;
        float v0 = s0 * inv + b2[0] + g_rr[base + 0];
        float v1 = s1 * inv + b2[1] + g_rr[base + 1];
        float v2 = s2 * inv + b2[2] + g_rr[base + 2];
        float v3 = s3 * inv + b2[3] + g_rr[base + 3];
        float v4 = s4 * inv + b2[4] + g_rr[base + 4];
        float v5 = s5 * inv + b2[5] + g_rr[base + 5];
        atomicMax(&zmax[0], encf(v0));
        atomicMax(&zmax[1], encf(v1));
        atomicMax(&zmax[2], encf(v2));
        atomicMax(&zmax[3], encf(v3));
        atomicMax(&zmax[4], encf(v4));
        atomicMax(&zmax[5], encf(v5));
    }
    __syncthreads();
    if (threadIdx.x < 6) atomicMax(&g_zenc[t * 8 + threadIdx.x], zmax[threadIdx.x]);
}

// ---------------- K7: GRU + NCE + outputs (single block) ----------------
__global__ void k7_final(const float* __restrict__ wih,
                         const float* __restrict__ bih,
                         const float* __restrict__ bhh,
                         float* __restrict__ out, int out_size)
{
    __shared__ float z[T * 6];
    __shared__ float gout[30 * 6];
    __shared__ float redf[256];
    __shared__ int   redi[256];
    int tid = threadIdx.x;
    for (int idx = tid; idx < T * 6; idx += 256)
        z[idx] = decf(g_zenc[(idx / 6) * 8 + (idx % 6)]);
    __syncthreads();
    if (tid < 180) {
        int t = tid / 6, j = tid % 6;
        float ar = 0.f, au = 0.f, an = 0.f;
#pragma unroll
        for (int d = 0; d < 6; d++) {
            float zv = z[t * 6 + d];
            ar += zv * wih[(0 + j) * 6 + d];
            au += zv * wih[(6 + j) * 6 + d];
            an += zv * wih[(12 + j) * 6 + d];
        }
        float r = 1.f / (1.f + expf(-(ar + bih[j]      + bhh[j])));
        float u = 1.f / (1.f + expf(-(au + bih[6 + j]  + bhh[6 + j])));
        float n = tanhf(an + bih[12 + j] + r * bhh[12 + j]);
        gout[tid] = (1.f - u) * n;
    }
    __syncthreads();
    float lnce = 0.f; int lc = 0;
    if (tid < 240) {
        int tp = tid / 12;           // 0..19
        int ii = tid % 12 + 1;       // 1..12
        int t = 10 + tp;
        const int joff[8] = {0, 11, 12, 13, 14, 15, 16, 17};
        float lg[8];
#pragma unroll
        for (int s = 0; s < 8; s++) {
            int idx = t + ii + joff[s];
            float d = 0.f;
#pragma unroll
            for (int c = 0; c < 6; c++) d += z[idx * 6 + c] * gout[t * 6 + c];
            lg[s] = d;
        }
        float m = lg[0];
#pragma unroll
        for (int s = 1; s < 8; s++) m = fmaxf(m, lg[s]);
        float se = 0.f;
#pragma unroll
        for (int s = 0; s < 8; s++) se += expf(lg[s] - m);
        lnce = lg[0] - m - logf(se);
        bool ok = true;
#pragma unroll
        for (int s = 1; s < 8; s++) if (lg[s] > lg[0]) ok = false;
        lc = ok ? 1 : 0;
    }
    redf[tid] = lnce; redi[tid] = lc;
    __syncthreads();
    for (int o = 128; o > 0; o >>= 1) {
        if (tid < o) { redf[tid] += redf[tid + o]; redi[tid] += redi[tid + o]; }
        __syncthreads();
    }
    if (tid == 0) {
        if (out_size > 0) out[0] = redf[0] / (-240.0f);
        if (out_size > 1) out[1] = (float)redi[0] / 240.0f;
    }
    if (tid < 180 && (2 + tid) < out_size) out[2 + tid] = gout[tid];
    for (int idx = 182 + tid; idx < out_size; idx += 256) out[idx] = 0.f;
}

// ---------------- launch ----------------
extern "C" void kernel_launch(void* const* d_in, const int* in_sizes, int n_in,
                              void* d_out, int out_size)
{
    const float* x   = (const float*)d_in[0];
    const int*   ei  = (const int*)  d_in[1];
    const float* W1l = (const float*)d_in[2];
    const float* W1r = (const float*)d_in[3];
    const float* b1  = (const float*)d_in[4];
    const float* W2l = (const float*)d_in[5];
    const float* W2r = (const float*)d_in[6];
    const float* b2  = (const float*)d_in[7];
    const float* wih = (const float*)d_in[8];
    // d_in[9] = gru_whh (unused: h0 == 0)
    const float* bih = (const float*)d_in[10];
    const float* bhh = (const float*)d_in[11];
    float* out = (float*)d_out;

    const int smemK4 = (64 * 128 * 2 + 128 + 8 * 512) * (int)sizeof(float); // 82432 B
    cudaFuncSetAttribute(k4_fused, cudaFuncAttributeMaxDynamicSharedMemorySize, smemK4);

    k0_init <<<(T * NN + 255) / 256, 256>>>();
    k1_build<<<(T * (EE / 4) + 255) / 256, 256>>>(ei);
    k4_fused<<<296, 256, smemK4>>>(x, W1l, W1r, b1, W2l, W2r);
    k6_layer2<<<T * ((NN + 255) / 256), 256>>>(b2);
    k7_final<<<1, 256>>>(wih, bih, bhh, out, out_size);
}

// round 5
// speedup vs baseline: 1.0678x; 1.0678x over previous
#include <cuda_runtime.h>
#include <cstdint>
#include <cstddef>
#include <math.h>

#define T    60
#define NN   10000
#define EE   160000
#define INC  64
#define HIDC 128
#define CAP  64
#define TOT  (T * NN)

// ---------------- scratch (static device globals; no allocation) ----------------
__device__ int      g_deg [TOT];
__device__ int      g_slot[(size_t)TOT * CAP];     // bucketed adjacency
__device__ float    g_mean[(size_t)TOT * INC];     // 153.6 MB
__device__ float    g_p   [(size_t)TOT * 8];       // layer-2 aggregand
__device__ float    g_rr  [(size_t)TOT * 8];       // self term of layer 2
__device__ unsigned g_zenc[T * 8];

__device__ __forceinline__ unsigned encf(float f) {
    unsigned u = __float_as_uint(f);
    return (u & 0x80000000u) ? ~u : (u | 0x80000000u);
}
__device__ __forceinline__ float decf(unsigned u) {
    return (u & 0x80000000u) ? __uint_as_float(u & 0x7fffffffu) : __uint_as_float(~u);
}

// ---------------- K0: init ----------------
__global__ void k0_init() {
    int idx = blockIdx.x * blockDim.x + threadIdx.x;
    if (idx < TOT) g_deg[idx] = 0;
    if (idx < T * 8) g_zenc[idx] = 0u;
}

// ---------------- K1: single-pass bucketed CSR build ----------------
__global__ void k1_build(const int* __restrict__ ei) {
    int q = blockIdx.x * blockDim.x + threadIdx.x;
    if (q >= T * (EE / 4)) return;
    int t = q / (EE / 4);
    int e = (q - t * (EE / 4)) * 4;
    const int* sp = ei + (size_t)t * 2 * EE + e;
    int4 sv = *(const int4*)sp;
    int4 dv = *(const int4*)(sp + EE);
    int tb = t * NN;
    int d0 = tb + dv.x, d1 = tb + dv.y, d2 = tb + dv.z, d3 = tb + dv.w;
    int p0 = atomicAdd(&g_deg[d0], 1);
    int p1 = atomicAdd(&g_deg[d1], 1);
    int p2 = atomicAdd(&g_deg[d2], 1);
    int p3 = atomicAdd(&g_deg[d3], 1);
    if (p0 < CAP) g_slot[(size_t)d0 * CAP + p0] = sv.x;
    if (p1 < CAP) g_slot[(size_t)d1 * CAP + p1] = sv.y;
    if (p2 < CAP) g_slot[(size_t)d2 * CAP + p2] = sv.z;
    if (p3 < CAP) g_slot[(size_t)d3 * CAP + p3] = sv.w;
}

// ---------------- K4a: layer-1 mean aggregation (warp per node) ----------------
__global__ void k4a_agg(const float* __restrict__ x) {
    int w = (blockIdx.x * blockDim.x + threadIdx.x) >> 5;
    int lane = threadIdx.x & 31;
    if (w >= TOT) return;
    int node = w;
    int t = node / NN;
    int deg = g_deg[node];
    int m = min(deg, CAP);
    const int* elist = g_slot + (size_t)node * CAP;
    const float* xt = x + (size_t)t * NN * INC;
    float sx = 0.f, sy = 0.f;
    int e = 0;
    for (; e + 4 <= m; e += 4) {
        int s0 = elist[e + 0], s1 = elist[e + 1], s2 = elist[e + 2], s3 = elist[e + 3];
        float2 v0 = ((const float2*)(xt + (size_t)s0 * INC))[lane];
        float2 v1 = ((const float2*)(xt + (size_t)s1 * INC))[lane];
        float2 v2 = ((const float2*)(xt + (size_t)s2 * INC))[lane];
        float2 v3 = ((const float2*)(xt + (size_t)s3 * INC))[lane];
        sx += (v0.x + v1.x) + (v2.x + v3.x);
        sy += (v0.y + v1.y) + (v2.y + v3.y);
    }
    for (; e < m; e++) {
        int s0 = elist[e];
        float2 v0 = ((const float2*)(xt + (size_t)s0 * INC))[lane];
        sx += v0.x; sy += v0.y;
    }
    float inv = 1.0f / (float)max(deg, 1);
    ((float2*)(g_mean + (size_t)node * INC))[lane] = make_float2(sx * inv, sy * inv);
}

// ---------------- K5: register-tiled SGEMM + fused layer-2 projection ----------------
// C[node][n] = relu([mean|x] @ [W1l|W1r].T + b1) ; p = C@W2l.T ; rr = C@W2r.T
// block: 256 thr = 8 warps; tile 128m x 128n; warp = 16m x 128n; thread 8m x 8n.
#define KCH 16   // k-chunk
__global__ __launch_bounds__(256, 2) void k5_gemm(
    const float* __restrict__ x,
    const float* __restrict__ W1l, const float* __restrict__ W1r,
    const float* __restrict__ b1,
    const float* __restrict__ W2l, const float* __restrict__ W2r)
{
    extern __shared__ float sm[];
    float* sB   = sm;            // [128 k][128 n]
    float* sA   = sm + 16384;    // [2][16 k][132 m]
    float* sW2l = sm + 20608;    // [6][128]
    float* sW2r = sm + 21376;    // [6][128]
    float* sB1  = sm + 22144;    // [128]
    int tid = threadIdx.x;

    // stage B (coalesced gmem reads)
    for (int idx = tid; idx < 8192; idx += 256) {
        int n = idx >> 6, c = idx & 63;
        sB[c * 128 + n]        = W1l[idx];
        sB[(64 + c) * 128 + n] = W1r[idx];
    }
    for (int idx = tid; idx < 768; idx += 256) {
        sW2l[idx] = W2l[idx];
        sW2r[idx] = W2r[idx];
    }
    if (tid < 128) sB1[tid] = b1[tid];

    int mbase = blockIdx.x * 128;
    int mrow  = tid >> 1;            // 0..127
    int chalf = (tid & 1) * 8;       // 0 or 8 within 16-chunk
    int nodeL = min(mbase + mrow, TOT - 1);

    // prefetch chunk 0 (k = 0..15 -> mean channels)
    float4 pf0, pf1;
    {
        const float* src = g_mean + (size_t)nodeL * 64 + chalf;
        pf0 = *(const float4*)(src);
        pf1 = *(const float4*)(src + 4);
    }
    // store chunk 0 into buf 0 (transposed)
    {
        float* dst = sA + chalf * 132 + mrow;
        dst[0 * 132] = pf0.x; dst[1 * 132] = pf0.y; dst[2 * 132] = pf0.z; dst[3 * 132] = pf0.w;
        dst[4 * 132] = pf1.x; dst[5 * 132] = pf1.y; dst[6 * 132] = pf1.z; dst[7 * 132] = pf1.w;
    }
    __syncthreads();

    int lane = tid & 31;
    int wm   = tid >> 5;         // warp id 0..7 -> m group
    int lm2  = lane >> 4;        // 0..1
    int ln16 = lane & 15;        // 0..15 -> covers all 128 n
    int mOff = wm * 16 + lm2 * 8;
    int nOff = ln16 * 8;

    float acc[8][8];
#pragma unroll
    for (int i = 0; i < 8; i++)
#pragma unroll
        for (int j = 0; j < 8; j++) acc[i][j] = 0.f;

#pragma unroll 1
    for (int cc = 0; cc < 8; cc++) {
        // prefetch next chunk
        if (cc < 7) {
            int c = (cc + 1) * 16 + chalf;
            const float* src = (c < 64) ? (g_mean + (size_t)nodeL * 64 + c)
                                        : (x + (size_t)nodeL * 64 + (c - 64));
            pf0 = *(const float4*)(src);
            pf1 = *(const float4*)(src + 4);
        }
        // compute over this chunk
        const float* Abuf = sA + (cc & 1) * 2112;
#pragma unroll
        for (int kk = 0; kk < KCH; kk++) {
            const float* Ar = Abuf + kk * 132 + mOff;
            float4 a0 = *(const float4*)(Ar);
            float4 a1 = *(const float4*)(Ar + 4);
            const float* Br = sB + (cc * 16 + kk) * 128 + nOff;
            float4 b0 = *(const float4*)(Br);
            float4 b1v = *(const float4*)(Br + 4);
            float av[8] = {a0.x, a0.y, a0.z, a0.w, a1.x, a1.y, a1.z, a1.w};
            float bv[8] = {b0.x, b0.y, b0.z, b0.w, b1v.x, b1v.y, b1v.z, b1v.w};
#pragma unroll
            for (int i = 0; i < 8; i++)
#pragma unroll
                for (int j = 0; j < 8; j++)
                    acc[i][j] += av[i] * bv[j];
        }
        // store prefetched chunk into other buffer
        if (cc < 7) {
            float* dst = sA + ((cc + 1) & 1) * 2112 + chalf * 132 + mrow;
            dst[0 * 132] = pf0.x; dst[1 * 132] = pf0.y; dst[2 * 132] = pf0.z; dst[3 * 132] = pf0.w;
            dst[4 * 132] = pf1.x; dst[5 * 132] = pf1.y; dst[6 * 132] = pf1.z; dst[7 * 132] = pf1.w;
        }
        __syncthreads();
    }

    // epilogue: bias + relu (in place)
    {
        const float* bp = sB1 + nOff;
        float4 bb0 = *(const float4*)(bp);
        float4 bb1 = *(const float4*)(bp + 4);
        float br[8] = {bb0.x, bb0.y, bb0.z, bb0.w, bb1.x, bb1.y, bb1.z, bb1.w};
#pragma unroll
        for (int i = 0; i < 8; i++)
#pragma unroll
            for (int j = 0; j < 8; j++)
                acc[i][j] = fmaxf(acc[i][j] + br[j], 0.f);
    }

    // layer-2 projection: per output channel jp, partial over this lane's 8 n,
    // then shfl-reduce over the 16 n-lanes; lane ln16==0 stores.
#pragma unroll
    for (int jp = 0; jp < 6; jp++) {
        const float* wl = sW2l + jp * 128 + nOff;
        const float* wr = sW2r + jp * 128 + nOff;
        float4 wl0 = *(const float4*)(wl);
        float4 wl1 = *(const float4*)(wl + 4);
        float4 wr0 = *(const float4*)(wr);
        float4 wr1 = *(const float4*)(wr + 4);
        float wlv[8] = {wl0.x, wl0.y, wl0.z, wl0.w, wl1.x, wl1.y, wl1.z, wl1.w};
        float wrv[8] = {wr0.x, wr0.y, wr0.z, wr0.w, wr1.x, wr1.y, wr1.z, wr1.w};
        float pvl[8], pvr[8];
#pragma unroll
        for (int i = 0; i < 8; i++) {
            float sl = 0.f, sr = 0.f;
#pragma unroll
            for (int j = 0; j < 8; j++) {
                sl += acc[i][j] * wlv[j];
                sr += acc[i][j] * wrv[j];
            }
            pvl[i] = sl; pvr[i] = sr;
        }
#pragma unroll
        for (int o = 1; o <= 8; o <<= 1) {
#pragma unroll
            for (int i = 0; i < 8; i++) {
                pvl[i] += __shfl_xor_sync(0xffffffffu, pvl[i], o);
                pvr[i] += __shfl_xor_sync(0xffffffffu, pvr[i], o);
            }
        }
        if (ln16 == 0) {
#pragma unroll
            for (int i = 0; i < 8; i++) {
                int node = mbase + mOff + i;
                if (node < TOT) {
                    g_p [(size_t)node * 8 + jp] = pvl[i];
                    g_rr[(size_t)node * 8 + jp] = pvr[i];
                }
            }
        }
    }
}

// ---------------- K6: layer-2 aggregation + global max pool (quarter-warp/node) ----------------
#define K6_CHUNKS 157   // ceil(10000 / 64)
__global__ void k6_layer2(const float* __restrict__ b2) {
    int t = blockIdx.x / K6_CHUNKS;
    int chunk = blockIdx.x % K6_CHUNKS;
    int i = chunk * 64 + (threadIdx.x >> 2);
    int q = threadIdx.x & 3;
    __shared__ unsigned zmax[6];
    if (threadIdx.x < 6) zmax[threadIdx.x] = 0u;
    __syncthreads();
    if (i < NN) {
        int node = t * NN + i;
        int deg = g_deg[node];
        int m = min(deg, CAP);
        const int* elist = g_slot + (size_t)node * CAP;
        int tb = t * NN;
        float s0 = 0, s1 = 0, s2 = 0, s3 = 0, s4 = 0, s5 = 0;
        for (int e = q; e < m; e += 4) {
            const float4* pp = (const float4*)(g_p + (size_t)(tb + elist[e]) * 8);
            float4 a = pp[0];
            float4 b = pp[1];
            s0 += a.x; s1 += a.y; s2 += a.z; s3 += a.w; s4 += b.x; s5 += b.y;
        }
#pragma unroll
        for (int o = 1; o <= 2; o <<= 1) {
            s0 += __shfl_xor_sync(0xffffffffu, s0, o);
            s1 += __shfl_xor_sync(0xffffffffu, s1, o);
            s2 += __shfl_xor_sync(0xffffffffu, s2, o);
            s3 += __shfl_xor_sync(0xffffffffu, s3, o);
            s4 += __shfl_xor_sync(0xffffffffu, s4, o);
            s5 += __shfl_xor_sync(0xffffffffu, s5, o);
        }
        if (q == 0) {
            float inv = 1.0f / (float)max(deg, 1);
            size_t base = (size_t)node * 8;
            atomicMax(&zmax[0], encf(s0 * inv + b2[0] + g_rr[base + 0]));
            atomicMax(&zmax[1], encf(s1 * inv + b2[1] + g_rr[base + 1]));
            atomicMax(&zmax[2], encf(s2 * inv + b2[2] + g_rr[base + 2]));
            atomicMax(&zmax[3], encf(s3 * inv + b2[3] + g_rr[base + 3]));
            atomicMax(&zmax[4], encf(s4 * inv + b2[4] + g_rr[base + 4]));
            atomicMax(&zmax[5], encf(s5 * inv + b2[5] + g_rr[base + 5]));
        }
    }
    __syncthreads();
    if (threadIdx.x < 6) atomicMax(&g_zenc[t * 8 + threadIdx.x], zmax[threadIdx.x]);
}

// ---------------- K7: GRU + NCE + outputs (single block) ----------------
__global__ void k7_final(const float* __restrict__ wih,
                         const float* __restrict__ bih,
                         const float* __restrict__ bhh,
                         float* __restrict__ out, int out_size)
{
    __shared__ float z[T * 6];
    __shared__ float gout[30 * 6];
    __shared__ float redf[256];
    __shared__ int   redi[256];
    int tid = threadIdx.x;
    for (int idx = tid; idx < T * 6; idx += 256)
        z[idx] = decf(g_zenc[(idx / 6) * 8 + (idx % 6)]);
    __syncthreads();
    if (tid < 180) {
        int t = tid / 6, j = tid % 6;
        float ar = 0.f, au = 0.f, an = 0.f;
#pragma unroll
        for (int d = 0; d < 6; d++) {
            float zv = z[t * 6 + d];
            ar += zv * wih[(0 + j) * 6 + d];
            au += zv * wih[(6 + j) * 6 + d];
            an += zv * wih[(12 + j) * 6 + d];
        }
        float r = 1.f / (1.f + expf(-(ar + bih[j]      + bhh[j])));
        float u = 1.f / (1.f + expf(-(au + bih[6 + j]  + bhh[6 + j])));
        float n = tanhf(an + bih[12 + j] + r * bhh[12 + j]);
        gout[tid] = (1.f - u) * n;
    }
    __syncthreads();
    float lnce = 0.f; int lc = 0;
    if (tid < 240) {
        int tp = tid / 12;
        int ii = tid % 12 + 1;
        int t = 10 + tp;
        const int joff[8] = {0, 11, 12, 13, 14, 15, 16, 17};
        float lg[8];
#pragma unroll
        for (int s = 0; s < 8; s++) {
            int idx = t + ii + joff[s];
            float d = 0.f;
#pragma unroll
            for (int c = 0; c < 6; c++) d += z[idx * 6 + c] * gout[t * 6 + c];
            lg[s] = d;
        }
        float m = lg[0];
#pragma unroll
        for (int s = 1; s < 8; s++) m = fmaxf(m, lg[s]);
        float se = 0.f;
#pragma unroll
        for (int s = 0; s < 8; s++) se += expf(lg[s] - m);
        lnce = lg[0] - m - logf(se);
        bool ok = true;
#pragma unroll
        for (int s = 1; s < 8; s++) if (lg[s] > lg[0]) ok = false;
        lc = ok ? 1 : 0;
    }
    redf[tid] = lnce; redi[tid] = lc;
    __syncthreads();
    for (int o = 128; o > 0; o >>= 1) {
        if (tid < o) { redf[tid] += redf[tid + o]; redi[tid] += redi[tid + o]; }
        __syncthreads();
    }
    if (tid == 0) {
        if (out_size > 0) out[0] = redf[0] / (-240.0f);
        if (out_size > 1) out[1] = (float)redi[0] / 240.0f;
    }
    if (tid < 180 && (2 + tid) < out_size) out[2 + tid] = gout[tid];
    for (int idx = 182 + tid; idx < out_size; idx += 256) out[idx] = 0.f;
}

// ---------------- launch ----------------
extern "C" void kernel_launch(void* const* d_in, const int* in_sizes, int n_in,
                              void* d_out, int out_size)
{
    const float* x   = (const float*)d_in[0];
    const int*   ei  = (const int*)  d_in[1];
    const float* W1l = (const float*)d_in[2];
    const float* W1r = (const float*)d_in[3];
    const float* b1  = (const float*)d_in[4];
    const float* W2l = (const float*)d_in[5];
    const float* W2r = (const float*)d_in[6];
    const float* b2  = (const float*)d_in[7];
    const float* wih = (const float*)d_in[8];
    const float* bih = (const float*)d_in[10];
    const float* bhh = (const float*)d_in[11];
    float* out = (float*)d_out;

    const int smemK5 = 22272 * (int)sizeof(float);   // 89088 B
    cudaFuncSetAttribute(k5_gemm, cudaFuncAttributeMaxDynamicSharedMemorySize, smemK5);

    k0_init <<<(TOT + 255) / 256, 256>>>();
    k1_build<<<(T * (EE / 4) + 255) / 256, 256>>>(ei);
    k4a_agg <<<(TOT * 32 + 255) / 256, 256>>>(x);
    k5_gemm <<<(TOT + 127) / 128, 256, smemK5>>>(x, W1l, W1r, b1, W2l, W2r);
    k6_layer2<<<T * K6_CHUNKS, 256>>>(b2);
    k7_final<<<1, 256>>>(wih, bih, bhh, out, out_size);
}

// round 7
// speedup vs baseline: 1.7477x; 1.6368x over previous
#include <cuda_runtime.h>
#include <cuda_bf16.h>
#include <cstdint>
#include <cstddef>
#include <math.h>

#define T    60
#define NN   10000
#define EE   160000
#define INC  64
#define CAP  64
#define TOT  (T * NN)
#define TILES ((TOT + 127) / 128)

#define KP   136        // padded K stride (bf16 elems); 272 B rows -> conflict-free frags
#define KPB  272

// ---------------- scratch ----------------
__device__ int      g_deg [TOT];
__device__ int      g_slot[(size_t)TOT * CAP];
__device__ float    g_mean[(size_t)TOT * INC];
__device__ float    g_p   [(size_t)TOT * 8];
__device__ float    g_rr  [(size_t)TOT * 8];
__device__ unsigned g_zenc[T * 8];

__device__ __forceinline__ unsigned encf(float f) {
    unsigned u = __float_as_uint(f);
    return (u & 0x80000000u) ? ~u : (u | 0x80000000u);
}
__device__ __forceinline__ float decf(unsigned u) {
    return (u & 0x80000000u) ? __uint_as_float(u & 0x7fffffffu) : __uint_as_float(~u);
}

// ---------------- K0: init ----------------
__global__ void k0_init() {
    int idx = blockIdx.x * blockDim.x + threadIdx.x;
    if (idx < TOT) g_deg[idx] = 0;
    if (idx < T * 8) g_zenc[idx] = 0u;
}

// ---------------- K1: single-pass bucketed CSR build ----------------
__global__ void k1_build(const int* __restrict__ ei) {
    int q = blockIdx.x * blockDim.x + threadIdx.x;
    if (q >= T * (EE / 4)) return;
    int t = q / (EE / 4);
    int e = (q - t * (EE / 4)) * 4;
    const int* sp = ei + (size_t)t * 2 * EE + e;
    int4 sv = *(const int4*)sp;
    int4 dv = *(const int4*)(sp + EE);
    int tb = t * NN;
    int d0 = tb + dv.x, d1 = tb + dv.y, d2 = tb + dv.z, d3 = tb + dv.w;
    int p0 = atomicAdd(&g_deg[d0], 1);
    int p1 = atomicAdd(&g_deg[d1], 1);
    int p2 = atomicAdd(&g_deg[d2], 1);
    int p3 = atomicAdd(&g_deg[d3], 1);
    if (p0 < CAP) g_slot[(size_t)d0 * CAP + p0] = sv.x;
    if (p1 < CAP) g_slot[(size_t)d1 * CAP + p1] = sv.y;
    if (p2 < CAP) g_slot[(size_t)d2 * CAP + p2] = sv.z;
    if (p3 < CAP) g_slot[(size_t)d3 * CAP + p3] = sv.w;
}

// ---------------- K4a: layer-1 mean aggregation (warp per node) ----------------
__global__ void k4a_agg(const float* __restrict__ x) {
    int w = (blockIdx.x * blockDim.x + threadIdx.x) >> 5;
    int lane = threadIdx.x & 31;
    if (w >= TOT) return;
    int node = w;
    int t = node / NN;
    int deg = g_deg[node];
    int m = min(deg, CAP);
    const int* elist = g_slot + (size_t)node * CAP;
    const float* xt = x + (size_t)t * NN * INC;
    float sx = 0.f, sy = 0.f;
    int e = 0;
    for (; e + 4 <= m; e += 4) {
        int s0 = elist[e + 0], s1 = elist[e + 1], s2 = elist[e + 2], s3 = elist[e + 3];
        float2 v0 = ((const float2*)(xt + (size_t)s0 * INC))[lane];
        float2 v1 = ((const float2*)(xt + (size_t)s1 * INC))[lane];
        float2 v2 = ((const float2*)(xt + (size_t)s2 * INC))[lane];
        float2 v3 = ((const float2*)(xt + (size_t)s3 * INC))[lane];
        sx += (v0.x + v1.x) + (v2.x + v3.x);
        sy += (v0.y + v1.y) + (v2.y + v3.y);
    }
    for (; e < m; e++) {
        int s0 = elist[e];
        float2 v0 = ((const float2*)(xt + (size_t)s0 * INC))[lane];
        sx += v0.x; sy += v0.y;
    }
    float inv = 1.0f / (float)max(deg, 1);
    ((float2*)(g_mean + (size_t)node * INC))[lane] = make_float2(sx * inv, sy * inv);
}

// ---------------- bf16 split helpers ----------------
__device__ __forceinline__ uint32_t pack2(float a, float b) {
    __nv_bfloat162 h = __floats2bfloat162_rn(a, b);
    return *(uint32_t*)&h;
}
// returns hi pack, writes residual pack
__device__ __forceinline__ void split2(float a, float b, uint32_t& hi, uint32_t& lo) {
    __nv_bfloat162 h = __floats2bfloat162_rn(a, b);
    float ra = a - __bfloat162float(h.x);
    float rb = b - __bfloat162float(h.y);
    hi = *(uint32_t*)&h;
    lo = pack2(ra, rb);
}

// mma.sync m16n8k16 bf16 (row.col), fp32 accum
__device__ __forceinline__ void mma16816(float* c,
    uint32_t a0, uint32_t a1, uint32_t a2, uint32_t a3, uint32_t b0, uint32_t b1)
{
    asm volatile(
        "mma.sync.aligned.m16n8k16.row.col.f32.bf16.bf16.f32 "
        "{%0,%1,%2,%3}, {%4,%5,%6,%7}, {%8,%9}, {%0,%1,%2,%3};"
        : "+f"(c[0]), "+f"(c[1]), "+f"(c[2]), "+f"(c[3])
        : "r"(a0), "r"(a1), "r"(a2), "r"(a3), "r"(b0), "r"(b1));
}

// smem byte offsets
#define S_BH   0
#define S_BL   34816
#define S_AH   69632
#define S_AL   104448
#define S_W2T  139264    // [128 cols][12] f32
#define S_B1   145408    // [128] f32
#define S_TOTAL 145920

// ---------------- K5: HMMA bf16-split GEMM + fused layer-2 projection ----------------
// per tile: 128 nodes x 128 hidden, K = 128 ([mean|x]).
// D = Ah*Bh + Ah*Bl + Al*Bh ; then p/rr = relu(D + b1) @ [W2l|W2r].T
__global__ __launch_bounds__(256, 1) void k5_mma(
    const float* __restrict__ x,
    const float* __restrict__ W1l, const float* __restrict__ W1r,
    const float* __restrict__ b1,
    const float* __restrict__ W2l, const float* __restrict__ W2r)
{
    extern __shared__ __align__(16) char smem[];
    int tid = threadIdx.x, wid = tid >> 5, lane = tid & 31;
    int gidq = lane >> 2;      // groupID 0..7
    int tig  = lane & 3;       // 0..3

    // ---- stage B = [W1l | W1r] hi/lo (once per CTA) ----
    for (int idx = tid; idx < 128 * 128; idx += 256) {
        int n = idx >> 7, k = idx & 127;
        float w = (k < 64) ? W1l[n * 64 + k] : W1r[n * 64 + (k - 64)];
        __nv_bfloat16 h = __float2bfloat16(w);
        float r = w - __bfloat162float(h);
        __nv_bfloat16 l = __float2bfloat16(r);
        *(__nv_bfloat16*)(smem + S_BH + n * KPB + k * 2) = h;
        *(__nv_bfloat16*)(smem + S_BL + n * KPB + k * 2) = l;
    }
    // W2 transposed: [col][0..5]=W2l[j][col], [6..11]=W2r[j][col]
    for (int idx = tid; idx < 128 * 12; idx += 256) {
        int c = idx / 12, j = idx % 12;
        float w = (j < 6) ? W2l[j * 128 + c] : W2r[(j - 6) * 128 + c];
        *(float*)(smem + S_W2T + (size_t)(c * 12 + j) * 4) = w;
    }
    if (tid < 128) *(float*)(smem + S_B1 + tid * 4) = b1[tid];

    int rowStage = tid >> 1;     // 0..127
    int half = tid & 1;          // 0 = mean cols 0..63, 1 = x cols 64..127
    int row0 = wid * 16 + gidq;  // this thread's accumulator rows: row0, row0+8

    for (int tile = blockIdx.x; tile < TILES; tile += gridDim.x) {
        // ---- stage A (split hi/lo) ----
        {
            int node = min(tile * 128 + rowStage, TOT - 1);
            const float* src = half ? (x + (size_t)node * 64) : (g_mean + (size_t)node * 64);
#pragma unroll
            for (int g = 0; g < 8; g++) {
                float4 f0 = *(const float4*)(src + g * 8);
                float4 f1 = *(const float4*)(src + g * 8 + 4);
                uint32_t h0, h1, h2, h3, l0, l1, l2, l3;
                split2(f0.x, f0.y, h0, l0);
                split2(f0.z, f0.w, h1, l1);
                split2(f1.x, f1.y, h2, l2);
                split2(f1.z, f1.w, h3, l3);
                int off = rowStage * KPB + (half * 64 + g * 8) * 2;
                *(uint4*)(smem + S_AH + off) = make_uint4(h0, h1, h2, h3);
                *(uint4*)(smem + S_AL + off) = make_uint4(l0, l1, l2, l3);
            }
        }
        __syncthreads();

        // ---- compute: 8 k-steps of k16 ----
        float acc[16][4];
#pragma unroll
        for (int nt = 0; nt < 16; nt++)
#pragma unroll
            for (int e = 0; e < 4; e++) acc[nt][e] = 0.f;

#pragma unroll
        for (int ks = 0; ks < 8; ks++) {
            int kb = ks * 16;
            int ao = row0 * KPB + (kb + tig * 2) * 2;
            uint32_t ah0 = *(const uint32_t*)(smem + S_AH + ao);
            uint32_t ah1 = *(const uint32_t*)(smem + S_AH + ao + 8 * KPB);
            uint32_t ah2 = *(const uint32_t*)(smem + S_AH + ao + 16);
            uint32_t ah3 = *(const uint32_t*)(smem + S_AH + ao + 8 * KPB + 16);
            uint32_t al0 = *(const uint32_t*)(smem + S_AL + ao);
            uint32_t al1 = *(const uint32_t*)(smem + S_AL + ao + 8 * KPB);
            uint32_t al2 = *(const uint32_t*)(smem + S_AL + ao + 16);
            uint32_t al3 = *(const uint32_t*)(smem + S_AL + ao + 8 * KPB + 16);
#pragma unroll
            for (int nt = 0; nt < 16; nt++) {
                int bo = (nt * 8 + gidq) * KPB + (kb + tig * 2) * 2;
                uint32_t bh0 = *(const uint32_t*)(smem + S_BH + bo);
                uint32_t bh1 = *(const uint32_t*)(smem + S_BH + bo + 16);
                uint32_t bl0 = *(const uint32_t*)(smem + S_BL + bo);
                uint32_t bl1 = *(const uint32_t*)(smem + S_BL + bo + 16);
                mma16816(acc[nt], ah0, ah1, ah2, ah3, bh0, bh1);
                mma16816(acc[nt], ah0, ah1, ah2, ah3, bl0, bl1);
                mma16816(acc[nt], al0, al1, al2, al3, bh0, bh1);
            }
        }

        // ---- epilogue: bias + relu + W2 projection, reduce over tig ----
        float pl0[6] = {0,0,0,0,0,0}, pr0[6] = {0,0,0,0,0,0};
        float pl1[6] = {0,0,0,0,0,0}, pr1[6] = {0,0,0,0,0,0};
#pragma unroll
        for (int nt = 0; nt < 16; nt++) {
#pragma unroll
            for (int e = 0; e < 2; e++) {
                int col = nt * 8 + tig * 2 + e;
                float bb = *(const float*)(smem + S_B1 + col * 4);
                float h0 = fmaxf(acc[nt][e] + bb, 0.f);       // row0
                float h1 = fmaxf(acc[nt][2 + e] + bb, 0.f);   // row0+8
                const float* wv = (const float*)(smem + S_W2T + (size_t)col * 48);
                float4 w0 = *(const float4*)wv;
                float4 w1 = *(const float4*)(wv + 4);
                float4 w2 = *(const float4*)(wv + 8);
                pl0[0] += h0 * w0.x; pl0[1] += h0 * w0.y; pl0[2] += h0 * w0.z; pl0[3] += h0 * w0.w;
                pl0[4] += h0 * w1.x; pl0[5] += h0 * w1.y;
                pr0[0] += h0 * w1.z; pr0[1] += h0 * w1.w;
                pr0[2] += h0 * w2.x; pr0[3] += h0 * w2.y; pr0[4] += h0 * w2.z; pr0[5] += h0 * w2.w;
                pl1[0] += h1 * w0.x; pl1[1] += h1 * w0.y; pl1[2] += h1 * w0.z; pl1[3] += h1 * w0.w;
                pl1[4] += h1 * w1.x; pl1[5] += h1 * w1.y;
                pr1[0] += h1 * w1.z; pr1[1] += h1 * w1.w;
                pr1[2] += h1 * w2.x; pr1[3] += h1 * w2.y; pr1[4] += h1 * w2.z; pr1[5] += h1 * w2.w;
            }
        }
#pragma unroll
        for (int o = 1; o <= 2; o <<= 1) {
#pragma unroll
            for (int j = 0; j < 6; j++) {
                pl0[j] += __shfl_xor_sync(0xffffffffu, pl0[j], o);
                pr0[j] += __shfl_xor_sync(0xffffffffu, pr0[j], o);
                pl1[j] += __shfl_xor_sync(0xffffffffu, pl1[j], o);
                pr1[j] += __shfl_xor_sync(0xffffffffu, pr1[j], o);
            }
        }
        if (tig == 0) {
            int n0 = tile * 128 + row0;
            if (n0 < TOT) {
                float* gp = g_p + (size_t)n0 * 8;
                *(float4*)gp = make_float4(pl0[0], pl0[1], pl0[2], pl0[3]);
                *(float2*)(gp + 4) = make_float2(pl0[4], pl0[5]);
                float* gr = g_rr + (size_t)n0 * 8;
                *(float4*)gr = make_float4(pr0[0], pr0[1], pr0[2], pr0[3]);
                *(float2*)(gr + 4) = make_float2(pr0[4], pr0[5]);
            }
            int n1 = n0 + 8;
            if (n1 < TOT) {
                float* gp = g_p + (size_t)n1 * 8;
                *(float4*)gp = make_float4(pl1[0], pl1[1], pl1[2], pl1[3]);
                *(float2*)(gp + 4) = make_float2(pl1[4], pl1[5]);
                float* gr = g_rr + (size_t)n1 * 8;
                *(float4*)gr = make_float4(pr1[0], pr1[1], pr1[2], pr1[3]);
                *(float2*)(gr + 4) = make_float2(pr1[4], pr1[5]);
            }
        }
        __syncthreads();   // before next tile's A restage
    }
}

// ---------------- K6: layer-2 aggregation + global max pool ----------------
#define K6_CHUNKS 157
__global__ void k6_layer2(const float* __restrict__ b2) {
    int t = blockIdx.x / K6_CHUNKS;
    int chunk = blockIdx.x % K6_CHUNKS;
    int i = chunk * 64 + (threadIdx.x >> 2);
    int q = threadIdx.x & 3;
    __shared__ unsigned zmax[6];
    if (threadIdx.x < 6) zmax[threadIdx.x] = 0u;
    __syncthreads();
    if (i < NN) {
        int node = t * NN + i;
        int deg = g_deg[node];
        int m = min(deg, CAP);
        const int* elist = g_slot + (size_t)node * CAP;
        int tb = t * NN;
        float s0 = 0, s1 = 0, s2 = 0, s3 = 0, s4 = 0, s5 = 0;
        for (int e = q; e < m; e += 4) {
            const float4* pp = (const float4*)(g_p + (size_t)(tb + elist[e]) * 8);
            float4 a = pp[0];
            float4 b = pp[1];
            s0 += a.x; s1 += a.y; s2 += a.z; s3 += a.w; s4 += b.x; s5 += b.y;
        }
#pragma unroll
        for (int o = 1; o <= 2; o <<= 1) {
            s0 += __shfl_xor_sync(0xffffffffu, s0, o);
            s1 += __shfl_xor_sync(0xffffffffu, s1, o);
            s2 += __shfl_xor_sync(0xffffffffu, s2, o);
            s3 += __shfl_xor_sync(0xffffffffu, s3, o);
            s4 += __shfl_xor_sync(0xffffffffu, s4, o);
            s5 += __shfl_xor_sync(0xffffffffu, s5, o);
        }
        if (q == 0) {
            float inv = 1.0f / (float)max(deg, 1);
            size_t base = (size_t)node * 8;
            atomicMax(&zmax[0], encf(s0 * inv + b2[0] + g_rr[base + 0]));
            atomicMax(&zmax[1], encf(s1 * inv + b2[1] + g_rr[base + 1]));
            atomicMax(&zmax[2], encf(s2 * inv + b2[2] + g_rr[base + 2]));
            atomicMax(&zmax[3], encf(s3 * inv + b2[3] + g_rr[base + 3]));
            atomicMax(&zmax[4], encf(s4 * inv + b2[4] + g_rr[base + 4]));
            atomicMax(&zmax[5], encf(s5 * inv + b2[5] + g_rr[base + 5]));
        }
    }
    __syncthreads();
    if (threadIdx.x < 6) atomicMax(&g_zenc[t * 8 + threadIdx.x], zmax[threadIdx.x]);
}

// ---------------- K7: GRU + NCE + outputs ----------------
__global__ void k7_final(const float* __restrict__ wih,
                         const float* __restrict__ bih,
                         const float* __restrict__ bhh,
                         float* __restrict__ out, int out_size)
{
    __shared__ float z[T * 6];
    __shared__ float gout[30 * 6];
    __shared__ float redf[256];
    __shared__ int   redi[256];
    int tid = threadIdx.x;
    for (int idx = tid; idx < T * 6; idx += 256)
        z[idx] = decf(g_zenc[(idx / 6) * 8 + (idx % 6)]);
    __syncthreads();
    if (tid < 180) {
        int t = tid / 6, j = tid % 6;
        float ar = 0.f, au = 0.f, an = 0.f;
#pragma unroll
        for (int d = 0; d < 6; d++) {
            float zv = z[t * 6 + d];
            ar += zv * wih[(0 + j) * 6 + d];
            au += zv * wih[(6 + j) * 6 + d];
            an += zv * wih[(12 + j) * 6 + d];
        }
        float r = 1.f / (1.f + expf(-(ar + bih[j]      + bhh[j])));
        float u = 1.f / (1.f + expf(-(au + bih[6 + j]  + bhh[6 + j])));
        float n = tanhf(an + bih[12 + j] + r * bhh[12 + j]);
        gout[tid] = (1.f - u) * n;
    }
    __syncthreads();
    float lnce = 0.f; int lc = 0;
    if (tid < 240) {
        int tp = tid / 12;
        int ii = tid % 12 + 1;
        int t = 10 + tp;
        const int joff[8] = {0, 11, 12, 13, 14, 15, 16, 17};
        float lg[8];
#pragma unroll
        for (int s = 0; s < 8; s++) {
            int idx = t + ii + joff[s];
            float d = 0.f;
#pragma unroll
            for (int c = 0; c < 6; c++) d += z[idx * 6 + c] * gout[t * 6 + c];
            lg[s] = d;
        }
        float m = lg[0];
#pragma unroll
        for (int s = 1; s < 8; s++) m = fmaxf(m, lg[s]);
        float se = 0.f;
#pragma unroll
        for (int s = 0; s < 8; s++) se += expf(lg[s] - m);
        lnce = lg[0] - m - logf(se);
        bool ok = true;
#pragma unroll
        for (int s = 1; s < 8; s++) if (lg[s] > lg[0]) ok = false;
        lc = ok ? 1 : 0;
    }
    redf[tid] = lnce; redi[tid] = lc;
    __syncthreads();
    for (int o = 128; o > 0; o >>= 1) {
        if (tid < o) { redf[tid] += redf[tid + o]; redi[tid] += redi[tid + o]; }
        __syncthreads();
    }
    if (tid == 0) {
        if (out_size > 0) out[0] = redf[0] / (-240.0f);
        if (out_size > 1) out[1] = (float)redi[0] / 240.0f;
    }
    if (tid < 180 && (2 + tid) < out_size) out[2 + tid] = gout[tid];
    for (int idx = 182 + tid; idx < out_size; idx += 256) out[idx] = 0.f;
}

// ---------------- launch ----------------
extern "C" void kernel_launch(void* const* d_in, const int* in_sizes, int n_in,
                              void* d_out, int out_size)
{
    const float* x   = (const float*)d_in[0];
    const int*   ei  = (const int*)  d_in[1];
    const float* W1l = (const float*)d_in[2];
    const float* W1r = (const float*)d_in[3];
    const float* b1  = (const float*)d_in[4];
    const float* W2l = (const float*)d_in[5];
    const float* W2r = (const float*)d_in[6];
    const float* b2  = (const float*)d_in[7];
    const float* wih = (const float*)d_in[8];
    const float* bih = (const float*)d_in[10];
    const float* bhh = (const float*)d_in[11];
    float* out = (float*)d_out;

    cudaFuncSetAttribute(k5_mma, cudaFuncAttributeMaxDynamicSharedMemorySize, S_TOTAL);

    k0_init <<<(TOT + 255) / 256, 256>>>();
    k1_build<<<(T * (EE / 4) + 255) / 256, 256>>>(ei);
    k4a_agg <<<(TOT * 32 + 255) / 256, 256>>>(x);
    k5_mma  <<<148, 256, S_TOTAL>>>(x, W1l, W1r, b1, W2l, W2r);
    k6_layer2<<<T * K6_CHUNKS, 256>>>(b2);
    k7_final<<<1, 256>>>(wih, bih, bhh, out, out_size);
}